// round 1
// baseline (speedup 1.0000x reference)
#include <cuda_runtime.h>

// Problem constants
#define B_   2
#define N_   4096
#define E_   256
#define H_   8
#define TAU_ 32
#define HD_  32
#define M_   (B_ * N_)                 // 8192 rows per projected matrix
#define SCALING 0.17677669529663687f   // HD^-0.5 = 1/sqrt(32)

// Scratch: projected Q, K, V (fp32), 3 * 8192 * 256 floats = 25.2 MB
__device__ float g_proj[3ull * M_ * E_];

// ---------------------------------------------------------------------------
// Projection GEMM: P = X @ W^T + bias   (M=8192, N=256, K=256), z selects X.
// 64x64 tile, BK=16, 256 threads, 4x4 register micro-tile.
// ---------------------------------------------------------------------------
__global__ void proj_kernel(const float* __restrict__ Q,
                            const float* __restrict__ K,
                            const float* __restrict__ V,
                            const float* __restrict__ W,
                            const float* __restrict__ bias) {
    __shared__ float As[16][68];   // [k][m], padded
    __shared__ float Bs[16][68];   // [k][n], padded

    const float* X = (blockIdx.z == 0) ? Q : (blockIdx.z == 1 ? K : V);
    float* P = g_proj + (size_t)blockIdx.z * (size_t)M_ * E_;

    const int tid  = threadIdx.x;
    const int m0   = blockIdx.y << 6;
    const int n0   = blockIdx.x << 6;
    const int tx   = tid & 15;
    const int ty   = tid >> 4;
    const int lrow = tid >> 2;          // 0..63
    const int lc4  = (tid & 3) << 2;    // 0,4,8,12

    float acc[4][4] = {{0.f, 0.f, 0.f, 0.f},
                       {0.f, 0.f, 0.f, 0.f},
                       {0.f, 0.f, 0.f, 0.f},
                       {0.f, 0.f, 0.f, 0.f}};

    for (int k0 = 0; k0 < E_; k0 += 16) {
        float4 a = *reinterpret_cast<const float4*>(
            &X[(size_t)(m0 + lrow) * E_ + k0 + lc4]);
        float4 w = *reinterpret_cast<const float4*>(
            &W[(size_t)(n0 + lrow) * E_ + k0 + lc4]);
        As[lc4 + 0][lrow] = a.x; As[lc4 + 1][lrow] = a.y;
        As[lc4 + 2][lrow] = a.z; As[lc4 + 3][lrow] = a.w;
        Bs[lc4 + 0][lrow] = w.x; Bs[lc4 + 1][lrow] = w.y;
        Bs[lc4 + 2][lrow] = w.z; Bs[lc4 + 3][lrow] = w.w;
        __syncthreads();

        #pragma unroll
        for (int kk = 0; kk < 16; kk++) {
            float4 av = *reinterpret_cast<const float4*>(&As[kk][ty << 2]);
            float4 bv = *reinterpret_cast<const float4*>(&Bs[kk][tx << 2]);
            float a4[4] = {av.x, av.y, av.z, av.w};
            float b4[4] = {bv.x, bv.y, bv.z, bv.w};
            #pragma unroll
            for (int i = 0; i < 4; i++)
                #pragma unroll
                for (int j = 0; j < 4; j++)
                    acc[i][j] += a4[i] * b4[j];
        }
        __syncthreads();
    }

    float4 bb = *reinterpret_cast<const float4*>(&bias[n0 + (tx << 2)]);
    #pragma unroll
    for (int i = 0; i < 4; i++) {
        float4 o;
        o.x = acc[i][0] + bb.x;
        o.y = acc[i][1] + bb.y;
        o.z = acc[i][2] + bb.z;
        o.w = acc[i][3] + bb.w;
        *reinterpret_cast<float4*>(
            &P[(size_t)(m0 + (ty << 2) + i) * E_ + n0 + (tx << 2)]) = o;
    }
}

// ---------------------------------------------------------------------------
// Sliding-window attention on projected tensors.
// One block = (batch b, head h, tile of 64 queries). Window rows
// [n0-31, n0+63] (95 rows) of Kp/Vp head-slice staged in smem; rows with
// global index < 0 use the bias vector (projection of the zero pad).
// ---------------------------------------------------------------------------
__global__ void attn_kernel(const float* __restrict__ bias,
                            float* __restrict__ out) {
    const int QT = 64;
    const int ROWS = QT + TAU_ - 1;   // 95

    __shared__ float sQ[QT][33];
    __shared__ float sK[ROWS][33];
    __shared__ float sV[ROWS][33];
    __shared__ float sS[QT][33];      // scores -> probs in place

    const int tid  = threadIdx.x;
    const int tile = blockIdx.x & 63;          // N/64 = 64 tiles
    const int h    = (blockIdx.x >> 6) & 7;
    const int b    = blockIdx.x >> 9;
    const int n0   = tile * QT;
    const int be   = h * HD_;

    const float* Qp = g_proj;
    const float* Kp = g_proj + (size_t)M_ * E_;
    const float* Vp = g_proj + 2ull * M_ * E_;

    // Stage K/V window rows (bias for pre-sequence pad rows)
    for (int idx = tid; idx < ROWS * HD_; idx += 256) {
        int i = idx >> 5, d = idx & 31;
        int r = n0 - (TAU_ - 1) + i;
        float kv, vv;
        if (r >= 0) {
            size_t off = ((size_t)(b * N_ + r)) * E_ + be + d;
            kv = Kp[off];
            vv = Vp[off];
        } else {
            kv = bias[be + d];
            vv = bias[be + d];
        }
        sK[i][d] = kv;
        sV[i][d] = vv;
    }
    // Stage Q tile
    for (int idx = tid; idx < QT * HD_; idx += 256) {
        int i = idx >> 5, d = idx & 31;
        sQ[i][d] = Qp[((size_t)(b * N_ + n0 + i)) * E_ + be + d];
    }
    __syncthreads();

    // Scores: window row for (query ql, t) is local index ql + t
    for (int it = tid; it < QT * TAU_; it += 256) {
        int ql = it >> 5, t = it & 31;
        float s = 0.f;
        #pragma unroll
        for (int d = 0; d < HD_; d++)
            s += sQ[ql][d] * sK[ql + t][d];
        sS[ql][t] = s * SCALING;
    }
    __syncthreads();

    // Softmax: one thread per query (32-wide window, serial is cheap)
    if (tid < QT) {
        float mx = -1e30f;
        #pragma unroll
        for (int t = 0; t < TAU_; t++) mx = fmaxf(mx, sS[tid][t]);
        float sum = 0.f;
        #pragma unroll
        for (int t = 0; t < TAU_; t++) {
            float e = __expf(sS[tid][t] - mx);
            sS[tid][t] = e;
            sum += e;
        }
        float inv = 1.f / sum;
        #pragma unroll
        for (int t = 0; t < TAU_; t++) sS[tid][t] *= inv;
    }
    __syncthreads();

    // Output: out[ql][d] = sum_t p[ql][t] * V[ql+t][d]
    for (int it = tid; it < QT * HD_; it += 256) {
        int ql = it >> 5, d = it & 31;
        float o = 0.f;
        #pragma unroll
        for (int t = 0; t < TAU_; t++)
            o += sS[ql][t] * sV[ql + t][d];
        out[((size_t)(b * N_ + n0 + ql)) * E_ + be + d] = o;
    }
}

// ---------------------------------------------------------------------------
// Launch
// ---------------------------------------------------------------------------
extern "C" void kernel_launch(void* const* d_in, const int* in_sizes, int n_in,
                              void* d_out, int out_size) {
    const float* query = (const float*)d_in[0];
    const float* key   = (const float*)d_in[1];
    const float* value = (const float*)d_in[2];
    const float* W     = (const float*)d_in[3];
    const float* bias  = (const float*)d_in[4];
    float* out = (float*)d_out;

    dim3 gProj(E_ / 64, M_ / 64, 3);   // (4, 128, 3)
    proj_kernel<<<gProj, 256>>>(query, key, value, W, bias);

    attn_kernel<<<B_ * H_ * (N_ / 64), 256>>>(bias, out);
}

// round 2
// speedup vs baseline: 1.0046x; 1.0046x over previous
#include <cuda_runtime.h>
#include <cstdint>

// Problem constants
#define B_   2
#define N_   4096
#define E_   256
#define H_   8
#define TAU_ 32
#define HD_  32
#define M_   (B_ * N_)                 // 8192 rows per projected matrix
#define SCALING 0.17677669529663687f   // HD^-0.5 = 1/sqrt(32)

// Scratch: projected Q, K, V (fp32), 3 * 8192 * 256 floats = 25.2 MB
__device__ float g_proj[3ull * M_ * E_];

// ---------------------------------------------------------------------------
// Split-TF32 helpers: x = hi + lo, hi has tf32 mantissa (mask low 13 bits),
// lo is the exact fp32 residual. MMA hardware reads tf32 (top 19 bits), so
// 3 products hi*hi + lo*hi + hi*lo recover ~fp32 accuracy.
// ---------------------------------------------------------------------------
__device__ __forceinline__ void split_tf32(float x, float& hi, float& lo) {
    hi = __uint_as_float(__float_as_uint(x) & 0xFFFFE000u);
    lo = x - hi;
}

__device__ __forceinline__ void mma_tf32(float c[4], const uint32_t a[4],
                                         const uint32_t b[2]) {
    asm volatile(
        "mma.sync.aligned.m16n8k8.row.col.f32.tf32.tf32.f32 "
        "{%0,%1,%2,%3}, {%4,%5,%6,%7}, {%8,%9}, {%0,%1,%2,%3};"
        : "+f"(c[0]), "+f"(c[1]), "+f"(c[2]), "+f"(c[3])
        : "r"(a[0]), "r"(a[1]), "r"(a[2]), "r"(a[3]), "r"(b[0]), "r"(b[1]));
}

// ---------------------------------------------------------------------------
// Projection GEMM: P = X @ W^T + bias  (M=8192, N=256, K=256), z selects X.
// Block tile 128x64, BK=16, 8 warps (4 M-warps x 2 N-warps), warp tile 32x32
// (2x4 grid of m16n8k8), 3 MMAs per step (split-tf32).
// ---------------------------------------------------------------------------
__global__ __launch_bounds__(256) void proj_kernel(
        const float* __restrict__ Q,
        const float* __restrict__ K,
        const float* __restrict__ V,
        const float* __restrict__ W,
        const float* __restrict__ bias) {
    __shared__ float sAh[128][17], sAl[128][17];
    __shared__ float sBh[64][17],  sBl[64][17];

    const float* X = (blockIdx.z == 0) ? Q : (blockIdx.z == 1 ? K : V);
    float* P = g_proj + (size_t)blockIdx.z * (size_t)M_ * E_;

    const int tid  = threadIdx.x;
    const int m0   = blockIdx.y << 7;
    const int n0   = blockIdx.x << 6;
    const int lane = tid & 31;
    const int warp = tid >> 5;
    const int g    = lane >> 2;     // group id 0..7
    const int tig  = lane & 3;      // thread in group 0..3
    const int wM   = warp & 3;      // 0..3 -> 32-row slab
    const int wN   = warp >> 2;     // 0..1 -> 32-col slab

    float acc[2][4][4];
    #pragma unroll
    for (int mi = 0; mi < 2; mi++)
        #pragma unroll
        for (int ni = 0; ni < 4; ni++)
            #pragma unroll
            for (int r = 0; r < 4; r++) acc[mi][ni][r] = 0.f;

    for (int k0 = 0; k0 < E_; k0 += 16) {
        // Stage A tile (128x16): 512 float4, 2 per thread
        #pragma unroll
        for (int i = 0; i < 2; i++) {
            int e   = tid + (i << 8);
            int row = e >> 2;
            int c   = (e & 3) << 2;
            float4 v = *reinterpret_cast<const float4*>(
                &X[(size_t)(m0 + row) * E_ + k0 + c]);
            float h, l;
            split_tf32(v.x, h, l); sAh[row][c + 0] = h; sAl[row][c + 0] = l;
            split_tf32(v.y, h, l); sAh[row][c + 1] = h; sAl[row][c + 1] = l;
            split_tf32(v.z, h, l); sAh[row][c + 2] = h; sAl[row][c + 2] = l;
            split_tf32(v.w, h, l); sAh[row][c + 3] = h; sAl[row][c + 3] = l;
        }
        // Stage B tile (64x16): 256 float4, 1 per thread
        {
            int row = tid >> 2;
            int c   = (tid & 3) << 2;
            float4 v = *reinterpret_cast<const float4*>(
                &W[(size_t)(n0 + row) * E_ + k0 + c]);
            float h, l;
            split_tf32(v.x, h, l); sBh[row][c + 0] = h; sBl[row][c + 0] = l;
            split_tf32(v.y, h, l); sBh[row][c + 1] = h; sBl[row][c + 1] = l;
            split_tf32(v.z, h, l); sBh[row][c + 2] = h; sBl[row][c + 2] = l;
            split_tf32(v.w, h, l); sBh[row][c + 3] = h; sBl[row][c + 3] = l;
        }
        __syncthreads();

        #pragma unroll
        for (int kk = 0; kk < 16; kk += 8) {
            uint32_t ah[2][4], al[2][4], bh[4][2], bl[4][2];
            #pragma unroll
            for (int mi = 0; mi < 2; mi++) {
                int rb = wM * 32 + mi * 16;
                ah[mi][0] = __float_as_uint(sAh[rb + g    ][kk + tig    ]);
                ah[mi][1] = __float_as_uint(sAh[rb + g + 8][kk + tig    ]);
                ah[mi][2] = __float_as_uint(sAh[rb + g    ][kk + tig + 4]);
                ah[mi][3] = __float_as_uint(sAh[rb + g + 8][kk + tig + 4]);
                al[mi][0] = __float_as_uint(sAl[rb + g    ][kk + tig    ]);
                al[mi][1] = __float_as_uint(sAl[rb + g + 8][kk + tig    ]);
                al[mi][2] = __float_as_uint(sAl[rb + g    ][kk + tig + 4]);
                al[mi][3] = __float_as_uint(sAl[rb + g + 8][kk + tig + 4]);
            }
            #pragma unroll
            for (int ni = 0; ni < 4; ni++) {
                int cb = wN * 32 + ni * 8;
                bh[ni][0] = __float_as_uint(sBh[cb + g][kk + tig    ]);
                bh[ni][1] = __float_as_uint(sBh[cb + g][kk + tig + 4]);
                bl[ni][0] = __float_as_uint(sBl[cb + g][kk + tig    ]);
                bl[ni][1] = __float_as_uint(sBl[cb + g][kk + tig + 4]);
            }
            #pragma unroll
            for (int mi = 0; mi < 2; mi++)
                #pragma unroll
                for (int ni = 0; ni < 4; ni++) {
                    mma_tf32(acc[mi][ni], ah[mi], bh[ni]);
                    mma_tf32(acc[mi][ni], al[mi], bh[ni]);
                    mma_tf32(acc[mi][ni], ah[mi], bl[ni]);
                }
        }
        __syncthreads();
    }

    // Epilogue: add bias, store. c0,c1 -> row g; c2,c3 -> row g+8; cols tig*2,+1
    #pragma unroll
    for (int mi = 0; mi < 2; mi++) {
        int row = m0 + wM * 32 + mi * 16 + g;
        #pragma unroll
        for (int ni = 0; ni < 4; ni++) {
            int col = n0 + wN * 32 + ni * 8 + tig * 2;
            float2 bb = *reinterpret_cast<const float2*>(&bias[col]);
            float2 o0 = {acc[mi][ni][0] + bb.x, acc[mi][ni][1] + bb.y};
            float2 o1 = {acc[mi][ni][2] + bb.x, acc[mi][ni][3] + bb.y};
            *reinterpret_cast<float2*>(&P[(size_t)row       * E_ + col]) = o0;
            *reinterpret_cast<float2*>(&P[(size_t)(row + 8) * E_ + col]) = o1;
        }
    }
}

// ---------------------------------------------------------------------------
// Sliding-window attention. Block = (b, h, 64-query tile), 256 threads.
// 4 threads per query: each computes 8 scores (Q row in registers), shuffle
// softmax within the quad, then 8 output dims. All smem traffic is float4;
// K/V row stride 36 floats tiles the 32 banks at the crossbar floor.
// ---------------------------------------------------------------------------
__global__ __launch_bounds__(256) void attn_kernel(
        const float* __restrict__ bias,
        float* __restrict__ out) {
    const int QT = 64, ROWS = QT + TAU_ - 1, S = 36;

    __shared__ float sQ[QT][S];      // pre-scaled by SCALING
    __shared__ float sK[ROWS][S];
    __shared__ float sV[ROWS][S];
    __shared__ float sP[QT][33];     // softmax probabilities

    const int tid  = threadIdx.x;
    const int tile = blockIdx.x & 63;
    const int h    = (blockIdx.x >> 6) & 7;
    const int b    = blockIdx.x >> 9;
    const int n0   = tile * QT;
    const int be   = h * HD_;

    const float* Qp = g_proj;
    const float* Kp = g_proj + (size_t)M_ * E_;
    const float* Vp = g_proj + 2ull * M_ * E_;

    // Stage K/V window rows [n0-31, n0+63]; pre-sequence rows = bias vector.
    for (int i = tid; i < ROWS * 8; i += 256) {
        int row = i >> 3, c = i & 7;
        int r = n0 - (TAU_ - 1) + row;
        float4 kv, vv;
        if (r >= 0) {
            size_t off = ((size_t)(b * N_ + r)) * E_ + be;
            kv = reinterpret_cast<const float4*>(&Kp[off])[c];
            vv = reinterpret_cast<const float4*>(&Vp[off])[c];
        } else {
            kv = reinterpret_cast<const float4*>(&bias[be])[c];
            vv = kv;
        }
        *reinterpret_cast<float4*>(&sK[row][c << 2]) = kv;
        *reinterpret_cast<float4*>(&sV[row][c << 2]) = vv;
    }
    // Stage Q tile, folding in SCALING
    for (int i = tid; i < QT * 8; i += 256) {
        int row = i >> 3, c = i & 7;
        float4 q = reinterpret_cast<const float4*>(
            &Qp[((size_t)(b * N_ + n0 + row)) * E_ + be])[c];
        q.x *= SCALING; q.y *= SCALING; q.z *= SCALING; q.w *= SCALING;
        *reinterpret_cast<float4*>(&sQ[row][c << 2]) = q;
    }
    __syncthreads();

    const int ql  = tid >> 2;    // query 0..63
    const int sub = tid & 3;     // quarter 0..3

    // Q row into registers (reused for 8 window positions)
    float4 qv[8];
    #pragma unroll
    for (int c = 0; c < 8; c++)
        qv[c] = *reinterpret_cast<const float4*>(&sQ[ql][c << 2]);

    // Scores for t = sub*8 .. sub*8+7
    float e[8];
    float mx = -1e30f;
    #pragma unroll
    for (int j = 0; j < 8; j++) {
        int kr = ql + sub * 8 + j;
        float s = 0.f;
        #pragma unroll
        for (int c = 0; c < 8; c++) {
            float4 kv = *reinterpret_cast<const float4*>(&sK[kr][c << 2]);
            s += qv[c].x * kv.x + qv[c].y * kv.y
               + qv[c].z * kv.z + qv[c].w * kv.w;
        }
        e[j] = s;
        mx = fmaxf(mx, s);
    }
    // Softmax across the 4-lane quad (lanes ^1, ^2 stay inside the quad)
    mx = fmaxf(mx, __shfl_xor_sync(0xffffffffu, mx, 1));
    mx = fmaxf(mx, __shfl_xor_sync(0xffffffffu, mx, 2));
    float sum = 0.f;
    #pragma unroll
    for (int j = 0; j < 8; j++) {
        e[j] = __expf(e[j] - mx);
        sum += e[j];
    }
    sum += __shfl_xor_sync(0xffffffffu, sum, 1);
    sum += __shfl_xor_sync(0xffffffffu, sum, 2);
    float inv = 1.f / sum;
    #pragma unroll
    for (int j = 0; j < 8; j++)
        sP[ql][sub * 8 + j] = e[j] * inv;
    __syncthreads();

    // Output: dims d = sub*8 .. sub*8+7
    const int d0 = sub << 3;
    float4 o0 = {0.f, 0.f, 0.f, 0.f};
    float4 o1 = {0.f, 0.f, 0.f, 0.f};
    #pragma unroll
    for (int t = 0; t < TAU_; t++) {
        float p = sP[ql][t];
        float4 v0 = *reinterpret_cast<const float4*>(&sV[ql + t][d0]);
        float4 v1 = *reinterpret_cast<const float4*>(&sV[ql + t][d0 + 4]);
        o0.x += p * v0.x; o0.y += p * v0.y; o0.z += p * v0.z; o0.w += p * v0.w;
        o1.x += p * v1.x; o1.y += p * v1.y; o1.z += p * v1.z; o1.w += p * v1.w;
    }
    float* orow = &out[((size_t)(b * N_ + n0 + ql)) * E_ + be + d0];
    *reinterpret_cast<float4*>(orow)     = o0;
    *reinterpret_cast<float4*>(orow + 4) = o1;
}

// ---------------------------------------------------------------------------
// Launch
// ---------------------------------------------------------------------------
extern "C" void kernel_launch(void* const* d_in, const int* in_sizes, int n_in,
                              void* d_out, int out_size) {
    const float* query = (const float*)d_in[0];
    const float* key   = (const float*)d_in[1];
    const float* value = (const float*)d_in[2];
    const float* W     = (const float*)d_in[3];
    const float* bias  = (const float*)d_in[4];
    float* out = (float*)d_out;

    dim3 gProj(E_ / 64, M_ / 128, 3);   // (4, 64, 3)
    proj_kernel<<<gProj, 256>>>(query, key, value, W, bias);

    attn_kernel<<<B_ * H_ * (N_ / 64), 256>>>(bias, out);
}

// round 6
// speedup vs baseline: 1.6860x; 1.6783x over previous
#include <cuda_runtime.h>
#include <cuda_bf16.h>
#include <cstdint>

// Problem constants
#define B_   2
#define N_   4096
#define E_   256
#define H_   8
#define TAU_ 32
#define HD_  32
#define M_   (B_ * N_)
#define SCALING 0.17677669529663687f

// Scratch: projected Q, K, V (fp32)
__device__ float g_proj[3ull * M_ * E_];

// ---------------------------------------------------------------------------
// bf16 split helpers: x = hi + lo (both bf16). hi = rn(x), lo = rn(x - hi).
// 3 MMA passes (hh + hl + lh) recover ~2^-17 relative accuracy per term.
// ---------------------------------------------------------------------------
__device__ __forceinline__ void split_bf16(float x, __nv_bfloat16& h,
                                           __nv_bfloat16& l) {
    h = __float2bfloat16(x);
    l = __float2bfloat16(x - __bfloat162float(h));
}

__device__ __forceinline__ void mma_bf16(float c[4], const uint32_t a[4],
                                         const uint32_t b[2]) {
    asm volatile(
        "mma.sync.aligned.m16n8k16.row.col.f32.bf16.bf16.f32 "
        "{%0,%1,%2,%3}, {%4,%5,%6,%7}, {%8,%9}, {%0,%1,%2,%3};"
        : "+f"(c[0]), "+f"(c[1]), "+f"(c[2]), "+f"(c[3])
        : "r"(a[0]), "r"(a[1]), "r"(a[2]), "r"(a[3]), "r"(b[0]), "r"(b[1]));
}

// ---------------------------------------------------------------------------
// Projection GEMM: P = X @ W^T + bias (M=8192, N=256, K=256), z selects X.
// Block tile 128x64, BK=32, 8 warps (4 M x 2 N), warp tile 32x32 =
// 2x4 m16n8k16, 3 split passes. Operands staged in smem as k-major bf16 so
// each fragment register is one aligned ld.shared.b32 (natural bf16 pair).
// ---------------------------------------------------------------------------
#define SA_STRIDE 36   // bf16 elements per row (32 + 4 pad)

__global__ __launch_bounds__(256) void proj_kernel(
        const float* __restrict__ Q,
        const float* __restrict__ K,
        const float* __restrict__ V,
        const float* __restrict__ W,
        const float* __restrict__ bias) {
    __shared__ __nv_bfloat16 sAh[128 * SA_STRIDE];
    __shared__ __nv_bfloat16 sAl[128 * SA_STRIDE];
    __shared__ __nv_bfloat16 sBh[64 * SA_STRIDE];
    __shared__ __nv_bfloat16 sBl[64 * SA_STRIDE];

    const float* X = (blockIdx.z == 0) ? Q : (blockIdx.z == 1 ? K : V);
    float* P = g_proj + (size_t)blockIdx.z * (size_t)M_ * E_;

    const int tid  = threadIdx.x;
    const int m0   = blockIdx.y << 7;
    const int n0   = blockIdx.x << 6;
    const int lane = tid & 31;
    const int warp = tid >> 5;
    const int g    = lane >> 2;     // 0..7
    const int tig  = lane & 3;      // 0..3
    const int wM   = warp & 3;      // 0..3 -> 32-row slab
    const int wN   = warp >> 2;     // 0..1 -> 32-col slab

    float acc[2][4][4];
    #pragma unroll
    for (int mi = 0; mi < 2; mi++)
        #pragma unroll
        for (int ni = 0; ni < 4; ni++)
            #pragma unroll
            for (int r = 0; r < 4; r++) acc[mi][ni][r] = 0.f;

    #pragma unroll 1
    for (int k0 = 0; k0 < E_; k0 += 32) {
        __syncthreads();
        // Stage A chunk 128x32: 1024 float4, 4 per thread
        #pragma unroll
        for (int i = 0; i < 4; i++) {
            int e   = tid + (i << 8);
            int row = e >> 3;
            int c4  = (e & 7) << 2;
            float4 v = *reinterpret_cast<const float4*>(
                &X[(size_t)(m0 + row) * E_ + k0 + c4]);
            __nv_bfloat16 h[4], l[4];
            split_bf16(v.x, h[0], l[0]);
            split_bf16(v.y, h[1], l[1]);
            split_bf16(v.z, h[2], l[2]);
            split_bf16(v.w, h[3], l[3]);
            int o = row * SA_STRIDE + c4;
            *reinterpret_cast<ushort4*>(&sAh[o]) =
                make_ushort4(__bfloat16_as_ushort(h[0]), __bfloat16_as_ushort(h[1]),
                             __bfloat16_as_ushort(h[2]), __bfloat16_as_ushort(h[3]));
            *reinterpret_cast<ushort4*>(&sAl[o]) =
                make_ushort4(__bfloat16_as_ushort(l[0]), __bfloat16_as_ushort(l[1]),
                             __bfloat16_as_ushort(l[2]), __bfloat16_as_ushort(l[3]));
        }
        // Stage B chunk 64x32 (rows n0..n0+63 of W): 512 float4, 2 per thread
        #pragma unroll
        for (int i = 0; i < 2; i++) {
            int e   = tid + (i << 8);
            int row = e >> 3;
            int c4  = (e & 7) << 2;
            float4 v = *reinterpret_cast<const float4*>(
                &W[(size_t)(n0 + row) * E_ + k0 + c4]);
            __nv_bfloat16 h[4], l[4];
            split_bf16(v.x, h[0], l[0]);
            split_bf16(v.y, h[1], l[1]);
            split_bf16(v.z, h[2], l[2]);
            split_bf16(v.w, h[3], l[3]);
            int o = row * SA_STRIDE + c4;
            *reinterpret_cast<ushort4*>(&sBh[o]) =
                make_ushort4(__bfloat16_as_ushort(h[0]), __bfloat16_as_ushort(h[1]),
                             __bfloat16_as_ushort(h[2]), __bfloat16_as_ushort(h[3]));
            *reinterpret_cast<ushort4*>(&sBl[o]) =
                make_ushort4(__bfloat16_as_ushort(l[0]), __bfloat16_as_ushort(l[1]),
                             __bfloat16_as_ushort(l[2]), __bfloat16_as_ushort(l[3]));
        }
        __syncthreads();

        #pragma unroll
        for (int kk = 0; kk < 32; kk += 16) {
            uint32_t ah[2][4], al[2][4], bh[4][2], bl[4][2];
            #pragma unroll
            for (int mi = 0; mi < 2; mi++) {
                int r0 = (wM * 32 + mi * 16 + g) * SA_STRIDE + kk + 2 * tig;
                int r1 = r0 + 8 * SA_STRIDE;
                ah[mi][0] = *reinterpret_cast<const uint32_t*>(&sAh[r0]);
                ah[mi][1] = *reinterpret_cast<const uint32_t*>(&sAh[r1]);
                ah[mi][2] = *reinterpret_cast<const uint32_t*>(&sAh[r0 + 8]);
                ah[mi][3] = *reinterpret_cast<const uint32_t*>(&sAh[r1 + 8]);
                al[mi][0] = *reinterpret_cast<const uint32_t*>(&sAl[r0]);
                al[mi][1] = *reinterpret_cast<const uint32_t*>(&sAl[r1]);
                al[mi][2] = *reinterpret_cast<const uint32_t*>(&sAl[r0 + 8]);
                al[mi][3] = *reinterpret_cast<const uint32_t*>(&sAl[r1 + 8]);
            }
            #pragma unroll
            for (int ni = 0; ni < 4; ni++) {
                int c0 = (wN * 32 + ni * 8 + g) * SA_STRIDE + kk + 2 * tig;
                bh[ni][0] = *reinterpret_cast<const uint32_t*>(&sBh[c0]);
                bh[ni][1] = *reinterpret_cast<const uint32_t*>(&sBh[c0 + 8]);
                bl[ni][0] = *reinterpret_cast<const uint32_t*>(&sBl[c0]);
                bl[ni][1] = *reinterpret_cast<const uint32_t*>(&sBl[c0 + 8]);
            }
            #pragma unroll
            for (int mi = 0; mi < 2; mi++)
                #pragma unroll
                for (int ni = 0; ni < 4; ni++) {
                    mma_bf16(acc[mi][ni], ah[mi], bh[ni]);
                    mma_bf16(acc[mi][ni], ah[mi], bl[ni]);
                    mma_bf16(acc[mi][ni], al[mi], bh[ni]);
                }
        }
    }

    // Epilogue: c0,c1 -> row g cols 2tig,2tig+1; c2,c3 -> row g+8.
    #pragma unroll
    for (int mi = 0; mi < 2; mi++) {
        int row = m0 + wM * 32 + mi * 16 + g;
        #pragma unroll
        for (int ni = 0; ni < 4; ni++) {
            int col = n0 + wN * 32 + ni * 8 + tig * 2;
            float2 bb = *reinterpret_cast<const float2*>(&bias[col]);
            float2 o0 = {acc[mi][ni][0] + bb.x, acc[mi][ni][1] + bb.y};
            float2 o1 = {acc[mi][ni][2] + bb.x, acc[mi][ni][3] + bb.y};
            *reinterpret_cast<float2*>(&P[(size_t)row       * E_ + col]) = o0;
            *reinterpret_cast<float2*>(&P[(size_t)(row + 8) * E_ + col]) = o1;
        }
    }
}

// ---------------------------------------------------------------------------
// Sliding-window attention with query pairing.
// Block = (b, h, 64-query tile), 256 threads = 32 pairs x 8 threads.
// Thread t of pair p: queries (2p, 2p+1), t-slice [4t, 4t+4). The two
// queries' K rows overlap (5 loads serve 8 scores) and V rows overlap
// (33 loads serve both outputs). Q rows live in registers from gmem.
// ---------------------------------------------------------------------------
__global__ __launch_bounds__(256) void attn_kernel(
        const float* __restrict__ bias,
        float* __restrict__ out) {
    const int QT = 64, ROWS = QT + TAU_ - 1, S = 36;

    __shared__ float sK[ROWS][S];
    __shared__ float sV[ROWS][S];
    __shared__ float sP[QT][33];

    const int tid  = threadIdx.x;
    const int tile = blockIdx.x & 63;
    const int h    = (blockIdx.x >> 6) & 7;
    const int b    = blockIdx.x >> 9;
    const int n0   = tile * QT;
    const int be   = h * HD_;

    const float* Qp = g_proj;
    const float* Kp = g_proj + (size_t)M_ * E_;
    const float* Vp = g_proj + 2ull * M_ * E_;

    // Stage K/V window rows [n0-31, n0+63]; pre-sequence rows = bias vector.
    for (int i = tid; i < ROWS * 8; i += 256) {
        int row = i >> 3, c = i & 7;
        int r = n0 - (TAU_ - 1) + row;
        float4 kv, vv;
        if (r >= 0) {
            size_t off = ((size_t)(b * N_ + r)) * E_ + be;
            kv = reinterpret_cast<const float4*>(&Kp[off])[c];
            vv = reinterpret_cast<const float4*>(&Vp[off])[c];
        } else {
            kv = reinterpret_cast<const float4*>(&bias[be])[c];
            vv = kv;
        }
        *reinterpret_cast<float4*>(&sK[row][c << 2]) = kv;
        *reinterpret_cast<float4*>(&sV[row][c << 2]) = vv;
    }

    const int p    = tid >> 3;       // pair 0..31
    const int sub  = tid & 7;        // 0..7
    const int lq0  = p << 1;         // local query 2p
    const int t0   = sub << 2;       // 4 t-positions

    // Load both Q rows into registers (pre-scaled)
    float4 q0v[8], q1v[8];
    {
        const float* q0p = &Qp[((size_t)(b * N_ + n0 + lq0)) * E_ + be];
        #pragma unroll
        for (int c = 0; c < 8; c++) {
            float4 a = reinterpret_cast<const float4*>(q0p)[c];
            float4 bq = reinterpret_cast<const float4*>(q0p + E_)[c];
            a.x *= SCALING; a.y *= SCALING; a.z *= SCALING; a.w *= SCALING;
            bq.x *= SCALING; bq.y *= SCALING; bq.z *= SCALING; bq.w *= SCALING;
            q0v[c] = a; q1v[c] = bq;
        }
    }
    __syncthreads();

    // Scores: 5 K rows serve 4 scores for each query.
    // Row j (j=0..4) = sK[lq0 + t0 + j]. s0[j] (j<4) uses rows 0..3,
    // s1[j] uses rows 1..4.
    float s0[4], s1[4];
    #pragma unroll
    for (int j = 0; j < 4; j++) { s0[j] = 0.f; s1[j] = 0.f; }
    #pragma unroll
    for (int j = 0; j < 5; j++) {
        const float* kr = &sK[lq0 + t0 + j][0];
        float d0 = 0.f, d1 = 0.f;
        #pragma unroll
        for (int c = 0; c < 8; c++) {
            float4 kv = *reinterpret_cast<const float4*>(kr + (c << 2));
            d0 += q0v[c].x * kv.x + q0v[c].y * kv.y
                + q0v[c].z * kv.z + q0v[c].w * kv.w;
            d1 += q1v[c].x * kv.x + q1v[c].y * kv.y
                + q1v[c].z * kv.z + q1v[c].w * kv.w;
        }
        if (j < 4) s0[j] = d0;
        if (j > 0) s1[j - 1] = d1;
    }

    // Softmax across the 8 lanes of the pair-group (xor 1,2,4 stay inside)
    float mx0 = fmaxf(fmaxf(s0[0], s0[1]), fmaxf(s0[2], s0[3]));
    float mx1 = fmaxf(fmaxf(s1[0], s1[1]), fmaxf(s1[2], s1[3]));
    #pragma unroll
    for (int m = 1; m <= 4; m <<= 1) {
        mx0 = fmaxf(mx0, __shfl_xor_sync(0xffffffffu, mx0, m));
        mx1 = fmaxf(mx1, __shfl_xor_sync(0xffffffffu, mx1, m));
    }
    float sum0 = 0.f, sum1 = 0.f;
    #pragma unroll
    for (int j = 0; j < 4; j++) {
        s0[j] = __expf(s0[j] - mx0); sum0 += s0[j];
        s1[j] = __expf(s1[j] - mx1); sum1 += s1[j];
    }
    #pragma unroll
    for (int m = 1; m <= 4; m <<= 1) {
        sum0 += __shfl_xor_sync(0xffffffffu, sum0, m);
        sum1 += __shfl_xor_sync(0xffffffffu, sum1, m);
    }
    float inv0 = 1.f / sum0, inv1 = 1.f / sum1;
    #pragma unroll
    for (int j = 0; j < 4; j++) {
        sP[lq0][t0 + j]     = s0[j] * inv0;
        sP[lq0 + 1][t0 + j] = s1[j] * inv1;
    }
    __syncthreads();

    // Output: thread handles dims [4*sub, 4*sub+4) for both queries.
    // V rows lq0 + r, r=0..32: o0 uses r=0..31 (t=r), o1 uses r=1..32 (t=r-1).
    const int d0 = sub << 2;
    float4 o0 = {0.f, 0.f, 0.f, 0.f};
    float4 o1 = {0.f, 0.f, 0.f, 0.f};
    {
        // r = 0 (o0 only)
        float pr = sP[lq0][0];
        float4 v = *reinterpret_cast<const float4*>(&sV[lq0][d0]);
        o0.x += pr * v.x; o0.y += pr * v.y; o0.z += pr * v.z; o0.w += pr * v.w;
    }
    #pragma unroll
    for (int r = 1; r < 32; r++) {
        float4 v = *reinterpret_cast<const float4*>(&sV[lq0 + r][d0]);
        float p0r = sP[lq0][r];
        float p1r = sP[lq0 + 1][r - 1];
        o0.x += p0r * v.x; o0.y += p0r * v.y; o0.z += p0r * v.z; o0.w += p0r * v.w;
        o1.x += p1r * v.x; o1.y += p1r * v.y; o1.z += p1r * v.z; o1.w += p1r * v.w;
    }
    {
        // r = 32 (o1 only)
        float pr = sP[lq0 + 1][31];
        float4 v = *reinterpret_cast<const float4*>(&sV[lq0 + 32][d0]);
        o1.x += pr * v.x; o1.y += pr * v.y; o1.z += pr * v.z; o1.w += pr * v.w;
    }

    float* orow = &out[((size_t)(b * N_ + n0 + lq0)) * E_ + be + d0];
    *reinterpret_cast<float4*>(orow)      = o0;
    *reinterpret_cast<float4*>(orow + E_) = o1;
}

// ---------------------------------------------------------------------------
// Launch
// ---------------------------------------------------------------------------
extern "C" void kernel_launch(void* const* d_in, const int* in_sizes, int n_in,
                              void* d_out, int out_size) {
    const float* query = (const float*)d_in[0];
    const float* key   = (const float*)d_in[1];
    const float* value = (const float*)d_in[2];
    const float* W     = (const float*)d_in[3];
    const float* bias  = (const float*)d_in[4];
    float* out = (float*)d_out;

    dim3 gProj(E_ / 64, M_ / 128, 3);   // (4, 64, 3)
    proj_kernel<<<gProj, 256>>>(query, key, value, W, bias);

    attn_kernel<<<B_ * H_ * (N_ / 64), 256>>>(bias, out);
}